// round 5
// baseline (speedup 1.0000x reference)
#include <cuda_runtime.h>

#define N_NODES 50000
#define N_EDGES 1000000
#define D_IN    64
#define D_HID   64
#define D_OUTF  32

// ---- scratch (no allocs allowed). NOTE: device globals must ONLY be
// referenced from device code (never passed as kernel args from host). ----
__device__ float  g_deg [N_NODES];
__device__ float  g_dinv[N_NODES];
__device__ int    g_cnt [N_NODES];
__device__ int    g_rowstart[N_NODES + 1];
__device__ int    g_cursor[N_NODES];
__device__ float2 g_adj [N_EDGES];             // (src as int bits, w)
__device__ float  g_h   [N_NODES * D_HID];     // hs (pre-scaled by dinv)
__device__ float  g_agg [N_NODES * D_HID];     // layer-1 output

// ---------------- CSR build ----------------
__global__ void k_zero() {
    int i = blockIdx.x * blockDim.x + threadIdx.x;
    if (i < N_NODES) { g_cnt[i] = 0; g_deg[i] = 0.0f; }
}

__global__ void k_hist(const int* __restrict__ dst, const float* __restrict__ w) {
    int e = blockIdx.x * blockDim.x + threadIdx.x;
    if (e < N_EDGES) {
        int d = dst[e];
        atomicAdd(&g_cnt[d], 1);
        atomicAdd(&g_deg[d], w[e]);
    }
}

// single-block (256 threads) exclusive scan of g_cnt -> rowstart/cursor; also dinv.
// unroll 1: keep register pressure trivial, NO local-memory/stack use.
__global__ __launch_bounds__(256) void k_scan() {
    constexpr int NT  = 256;
    constexpr int PER = (N_NODES + NT - 1) / NT;   // 196
    __shared__ int bs[NT];
    int t = threadIdx.x;
    int base = t * PER;

    int s = 0;
#pragma unroll 1
    for (int i = 0; i < PER; i++) {
        int idx = base + i;
        if (idx < N_NODES) s += g_cnt[idx];
    }
    bs[t] = s;
    __syncthreads();
#pragma unroll 1
    for (int off = 1; off < NT; off <<= 1) {
        int v = (t >= off) ? bs[t - off] : 0;
        __syncthreads();
        bs[t] += v;
        __syncthreads();
    }
    int run = bs[t] - s;   // exclusive prefix

#pragma unroll 1
    for (int i = 0; i < PER; i++) {
        int idx = base + i;
        if (idx < N_NODES) {
            g_rowstart[idx] = run;
            g_cursor[idx]   = run;
            run += g_cnt[idx];
            g_dinv[idx] = rsqrtf(1.0f + g_deg[idx]);   // + self-loop
            if (idx == N_NODES - 1) g_rowstart[N_NODES] = run;
        }
    }
}

__global__ void k_permute(const int* __restrict__ src, const int* __restrict__ dst,
                          const float* __restrict__ w) {
    int e = blockIdx.x * blockDim.x + threadIdx.x;
    if (e < N_EDGES) {
        int d = dst[e];
        int p = atomicAdd(&g_cursor[d], 1);
        g_adj[p] = make_float2(__int_as_float(src[e]), w[e]);
    }
}

// ---------------- register-blocked GEMM + dinv scale ----------------
// DI = 64. Each thread computes a 4x4 tile. Writes hs = dinv*(X@W) to g_h.
template <int DO, int LAYER>
__global__ __launch_bounds__(256) void k_gemm_scale(
        const float* __restrict__ Xparam, const float* __restrict__ W) {
    constexpr int DI   = 64;
    constexpr int TX   = DO / 4;
    constexpr int TYN  = 256 / TX;
    constexpr int ROWS = TYN * 4;
    constexpr int XS   = ROWS + 4;

    __shared__ float Ws[DI * DO];
    __shared__ float xsT[DI * XS];

    const float* X = (LAYER == 1) ? Xparam : g_agg;   // device-side symbol ref: OK

    const int tid = threadIdx.x;
    const int tx  = tid % TX;
    const int ty  = tid / TX;
    const int blockRow = blockIdx.x * ROWS;

    for (int i = tid; i < DI * DO / 4; i += 256)
        reinterpret_cast<float4*>(Ws)[i] = reinterpret_cast<const float4*>(W)[i];

    for (int i = tid; i < ROWS * (DI / 4); i += 256) {
        int row = i / (DI / 4);
        int c4  = i % (DI / 4);
        int gr  = blockRow + row;
        float4 v = make_float4(0.f, 0.f, 0.f, 0.f);
        if (gr < N_NODES)
            v = reinterpret_cast<const float4*>(X + gr * DI)[c4];
        xsT[(c4 * 4 + 0) * XS + row] = v.x;
        xsT[(c4 * 4 + 1) * XS + row] = v.y;
        xsT[(c4 * 4 + 2) * XS + row] = v.z;
        xsT[(c4 * 4 + 3) * XS + row] = v.w;
    }
    __syncthreads();

    float acc[4][4];
#pragma unroll
    for (int i = 0; i < 4; i++)
#pragma unroll
        for (int j = 0; j < 4; j++) acc[i][j] = 0.0f;

#pragma unroll
    for (int k = 0; k < DI; k++) {
        float4 a = *reinterpret_cast<const float4*>(&xsT[k * XS + ty * 4]);
        float4 b = *reinterpret_cast<const float4*>(&Ws [k * DO + tx * 4]);
        acc[0][0] += a.x * b.x; acc[0][1] += a.x * b.y; acc[0][2] += a.x * b.z; acc[0][3] += a.x * b.w;
        acc[1][0] += a.y * b.x; acc[1][1] += a.y * b.y; acc[1][2] += a.y * b.z; acc[1][3] += a.y * b.w;
        acc[2][0] += a.z * b.x; acc[2][1] += a.z * b.y; acc[2][2] += a.z * b.z; acc[2][3] += a.z * b.w;
        acc[3][0] += a.w * b.x; acc[3][1] += a.w * b.y; acc[3][2] += a.w * b.z; acc[3][3] += a.w * b.w;
    }

#pragma unroll
    for (int i = 0; i < 4; i++) {
        int row = blockRow + ty * 4 + i;
        if (row >= N_NODES) break;
        float dv = g_dinv[row];
        float4 v = make_float4(dv * acc[i][0], dv * acc[i][1],
                               dv * acc[i][2], dv * acc[i][3]);
        *reinterpret_cast<float4*>(&g_h[row * DO + tx * 4]) = v;
    }
}

// ---------------- pull-gather: OUT[n] = relu(dinv_n*(hs_n + sum_e w*hs[src]) + b) ----
// LAYER==1 (D=64): writes g_agg (resolved in DEVICE code). One warp/node, lane owns float2.
__global__ __launch_bounds__(256) void k_gather64(const float* __restrict__ b) {
    int warp = (blockIdx.x * blockDim.x + threadIdx.x) >> 5;
    int lane = threadIdx.x & 31;
    if (warp >= N_NODES) return;
    int node = warp;

    int beg = g_rowstart[node];
    int end = g_rowstart[node + 1];

    float2 acc = *reinterpret_cast<const float2*>(&g_h[node * 64 + lane * 2]);  // self-loop
#pragma unroll 1
    for (int i = beg; i < end; i++) {
        float2 ew = g_adj[i];                 // broadcast across warp
        int   s  = __float_as_int(ew.x);
        float wv = ew.y;
        float2 hv = *reinterpret_cast<const float2*>(&g_h[s * 64 + lane * 2]);
        acc.x += wv * hv.x;
        acc.y += wv * hv.y;
    }
    float dv = g_dinv[node];
    float2 bb = *reinterpret_cast<const float2*>(&b[lane * 2]);
    float2 r  = make_float2(fmaxf(dv * acc.x + bb.x, 0.0f),
                            fmaxf(dv * acc.y + bb.y, 0.0f));
    *reinterpret_cast<float2*>(&g_agg[node * 64 + lane * 2]) = r;
}

// LAYER==2 (D=32): writes d_out (runtime pointer param — safe). One warp/node.
__global__ __launch_bounds__(256) void k_gather32(const float* __restrict__ b,
                                                  float* __restrict__ OUT) {
    int warp = (blockIdx.x * blockDim.x + threadIdx.x) >> 5;
    int lane = threadIdx.x & 31;
    if (warp >= N_NODES) return;
    int node = warp;

    int beg = g_rowstart[node];
    int end = g_rowstart[node + 1];

    float acc = g_h[node * 32 + lane];        // self-loop
#pragma unroll 1
    for (int i = beg; i < end; i++) {
        float2 ew = g_adj[i];
        int   s  = __float_as_int(ew.x);
        float wv = ew.y;
        acc += wv * g_h[s * 32 + lane];
    }
    float dv = g_dinv[node];
    OUT[node * 32 + lane] = fmaxf(dv * acc + b[lane], 0.0f);
}

extern "C" void kernel_launch(void* const* d_in, const int* in_sizes, int n_in,
                              void* d_out, int out_size) {
    const float* x   = (const float*)d_in[0];
    const int*   ei  = (const int*)  d_in[1];   // [2, E]
    const float* ew  = (const float*)d_in[2];
    const float* W1  = (const float*)d_in[3];
    const float* b1  = (const float*)d_in[4];
    const float* W2  = (const float*)d_in[5];
    const float* b2  = (const float*)d_in[6];
    float*       out = (float*)d_out;

    const int* src = ei;
    const int* dst = ei + N_EDGES;

    // CSR build + norm
    k_zero   <<<(N_NODES + 255) / 256, 256>>>();
    k_hist   <<<(N_EDGES + 255) / 256, 256>>>(dst, ew);
    k_scan   <<<1, 256>>>();
    k_permute<<<(N_EDGES + 255) / 256, 256>>>(src, dst, ew);

    // ---- layer 1 ----
    k_gemm_scale<D_HID, 1><<<(N_NODES + 63) / 64, 256>>>(x, W1);
    k_gather64<<<(N_NODES * 32 + 255) / 256, 256>>>(b1);

    // ---- layer 2 ----
    k_gemm_scale<D_OUTF, 2><<<(N_NODES + 127) / 128, 256>>>(nullptr, W2);
    k_gather32<<<(N_NODES * 32 + 255) / 256, 256>>>(b2, out);
}

// round 6
// speedup vs baseline: 1.1262x; 1.1262x over previous
#include <cuda_runtime.h>

#define N_NODES 50000
#define N_EDGES 1000000
#define D_IN    64
#define D_HID   64
#define D_OUTF  32

// ---- scratch (no allocs allowed). Device globals referenced ONLY in device code. ----
__device__ float  g_deg [N_NODES];
__device__ float  g_dinv[N_NODES];
__device__ int    g_cnt [N_NODES];
__device__ int    g_rowstart[N_NODES + 1];
__device__ int    g_cursor[N_NODES];
__device__ float2 g_adj [N_EDGES];             // (src as int bits, w), dst-grouped
__device__ float  g_h   [N_NODES * D_HID];     // hs (pre-scaled by dinv)
__device__ float  g_agg [N_NODES * D_HID];     // layer-1 output

// ---------------- CSR build ----------------
__global__ void k_zero() {
    int i = blockIdx.x * blockDim.x + threadIdx.x;
    if (i < N_NODES) { g_cnt[i] = 0; g_deg[i] = 0.0f; }
}

__global__ void k_hist(const int* __restrict__ dst, const float* __restrict__ w) {
    int e = blockIdx.x * blockDim.x + threadIdx.x;
    if (e < N_EDGES) {
        int d = dst[e];
        atomicAdd(&g_cnt[d], 1);
        atomicAdd(&g_deg[d], w[e]);
    }
}

// single-block (256 threads) exclusive scan of g_cnt -> rowstart/cursor; also dinv.
// unroll 1: trivial register pressure, no local-memory/stack (128MiB pool trap).
__global__ __launch_bounds__(256) void k_scan() {
    constexpr int NT  = 256;
    constexpr int PER = (N_NODES + NT - 1) / NT;   // 196
    __shared__ int bs[NT];
    int t = threadIdx.x;
    int base = t * PER;

    int s = 0;
#pragma unroll 1
    for (int i = 0; i < PER; i++) {
        int idx = base + i;
        if (idx < N_NODES) s += g_cnt[idx];
    }
    bs[t] = s;
    __syncthreads();
#pragma unroll 1
    for (int off = 1; off < NT; off <<= 1) {
        int v = (t >= off) ? bs[t - off] : 0;
        __syncthreads();
        bs[t] += v;
        __syncthreads();
    }
    int run = bs[t] - s;

#pragma unroll 1
    for (int i = 0; i < PER; i++) {
        int idx = base + i;
        if (idx < N_NODES) {
            g_rowstart[idx] = run;
            g_cursor[idx]   = run;
            run += g_cnt[idx];
            g_dinv[idx] = rsqrtf(1.0f + g_deg[idx]);   // + self-loop
            if (idx == N_NODES - 1) g_rowstart[N_NODES] = run;
        }
    }
}

__global__ void k_permute(const int* __restrict__ src, const int* __restrict__ dst,
                          const float* __restrict__ w) {
    int e = blockIdx.x * blockDim.x + threadIdx.x;
    if (e < N_EDGES) {
        int d = dst[e];
        int p = atomicAdd(&g_cursor[d], 1);
        g_adj[p] = make_float2(__int_as_float(src[e]), w[e]);
    }
}

// ---------------- register-blocked GEMM + dinv scale ----------------
template <int DO, int LAYER>
__global__ __launch_bounds__(256) void k_gemm_scale(
        const float* __restrict__ Xparam, const float* __restrict__ W) {
    constexpr int DI   = 64;
    constexpr int TX   = DO / 4;
    constexpr int TYN  = 256 / TX;
    constexpr int ROWS = TYN * 4;
    constexpr int XS   = ROWS + 4;

    __shared__ float Ws[DI * DO];
    __shared__ float xsT[DI * XS];

    const float* X = (LAYER == 1) ? Xparam : g_agg;

    const int tid = threadIdx.x;
    const int tx  = tid % TX;
    const int ty  = tid / TX;
    const int blockRow = blockIdx.x * ROWS;

    for (int i = tid; i < DI * DO / 4; i += 256)
        reinterpret_cast<float4*>(Ws)[i] = reinterpret_cast<const float4*>(W)[i];

    for (int i = tid; i < ROWS * (DI / 4); i += 256) {
        int row = i / (DI / 4);
        int c4  = i % (DI / 4);
        int gr  = blockRow + row;
        float4 v = make_float4(0.f, 0.f, 0.f, 0.f);
        if (gr < N_NODES)
            v = reinterpret_cast<const float4*>(X + gr * DI)[c4];
        xsT[(c4 * 4 + 0) * XS + row] = v.x;
        xsT[(c4 * 4 + 1) * XS + row] = v.y;
        xsT[(c4 * 4 + 2) * XS + row] = v.z;
        xsT[(c4 * 4 + 3) * XS + row] = v.w;
    }
    __syncthreads();

    float acc[4][4];
#pragma unroll
    for (int i = 0; i < 4; i++)
#pragma unroll
        for (int j = 0; j < 4; j++) acc[i][j] = 0.0f;

#pragma unroll
    for (int k = 0; k < DI; k++) {
        float4 a = *reinterpret_cast<const float4*>(&xsT[k * XS + ty * 4]);
        float4 b = *reinterpret_cast<const float4*>(&Ws [k * DO + tx * 4]);
        acc[0][0] += a.x * b.x; acc[0][1] += a.x * b.y; acc[0][2] += a.x * b.z; acc[0][3] += a.x * b.w;
        acc[1][0] += a.y * b.x; acc[1][1] += a.y * b.y; acc[1][2] += a.y * b.z; acc[1][3] += a.y * b.w;
        acc[2][0] += a.z * b.x; acc[2][1] += a.z * b.y; acc[2][2] += a.z * b.z; acc[2][3] += a.z * b.w;
        acc[3][0] += a.w * b.x; acc[3][1] += a.w * b.y; acc[3][2] += a.w * b.z; acc[3][3] += a.w * b.w;
    }

#pragma unroll
    for (int i = 0; i < 4; i++) {
        int row = blockRow + ty * 4 + i;
        if (row >= N_NODES) break;
        float dv = g_dinv[row];
        float4 v = make_float4(dv * acc[i][0], dv * acc[i][1],
                               dv * acc[i][2], dv * acc[i][3]);
        *reinterpret_cast<float4*>(&g_h[row * DO + tx * 4]) = v;
    }
}

// ---------------- pull-gather with shuffle-staged edges (high MLP) ----------------
// One warp per node. Edges for the node are loaded COALESCED (lane i takes edge
// beg+i), then broadcast via shfl so the h[src] gather addresses come from
// registers -> independent loads, batched by ptxas (unroll 4).

// LAYER 1, D=64: lane owns a float2 column pair; writes g_agg.
__global__ __launch_bounds__(256) void k_gather64(const float* __restrict__ b) {
    int node = (blockIdx.x * blockDim.x + threadIdx.x) >> 5;
    int lane = threadIdx.x & 31;
    if (node >= N_NODES) return;

    int beg = g_rowstart[node];
    int end = g_rowstart[node + 1];

    float2 acc = *reinterpret_cast<const float2*>(&g_h[node * 64 + lane * 2]);  // self-loop

#pragma unroll 1
    for (int base = beg; base < end; base += 32) {
        int n = end - base; if (n > 32) n = 32;
        float2 ev = make_float2(0.0f, 0.0f);
        if (lane < n) ev = g_adj[base + lane];          // coalesced 256B load
        int   evs = __float_as_int(ev.x);
#pragma unroll 4
        for (int j = 0; j < n; j++) {
            int   s  = __shfl_sync(0xffffffffu, evs,  j);
            float wv = __shfl_sync(0xffffffffu, ev.y, j);
            float2 hv = *reinterpret_cast<const float2*>(&g_h[s * 64 + lane * 2]);
            acc.x += wv * hv.x;
            acc.y += wv * hv.y;
        }
    }
    float dv = g_dinv[node];
    float2 bb = *reinterpret_cast<const float2*>(&b[lane * 2]);
    float2 r  = make_float2(fmaxf(dv * acc.x + bb.x, 0.0f),
                            fmaxf(dv * acc.y + bb.y, 0.0f));
    *reinterpret_cast<float2*>(&g_agg[node * 64 + lane * 2]) = r;
}

// LAYER 2, D=32: lane owns one column; writes d_out.
__global__ __launch_bounds__(256) void k_gather32(const float* __restrict__ b,
                                                  float* __restrict__ OUT) {
    int node = (blockIdx.x * blockDim.x + threadIdx.x) >> 5;
    int lane = threadIdx.x & 31;
    if (node >= N_NODES) return;

    int beg = g_rowstart[node];
    int end = g_rowstart[node + 1];

    float acc = g_h[node * 32 + lane];                  // self-loop

#pragma unroll 1
    for (int base = beg; base < end; base += 32) {
        int n = end - base; if (n > 32) n = 32;
        float2 ev = make_float2(0.0f, 0.0f);
        if (lane < n) ev = g_adj[base + lane];          // coalesced
        int   evs = __float_as_int(ev.x);
#pragma unroll 4
        for (int j = 0; j < n; j++) {
            int   s  = __shfl_sync(0xffffffffu, evs,  j);
            float wv = __shfl_sync(0xffffffffu, ev.y, j);
            acc += wv * g_h[s * 32 + lane];
        }
    }
    float dv = g_dinv[node];
    OUT[node * 32 + lane] = fmaxf(dv * acc + b[lane], 0.0f);
}

extern "C" void kernel_launch(void* const* d_in, const int* in_sizes, int n_in,
                              void* d_out, int out_size) {
    const float* x   = (const float*)d_in[0];
    const int*   ei  = (const int*)  d_in[1];   // [2, E]
    const float* ew  = (const float*)d_in[2];
    const float* W1  = (const float*)d_in[3];
    const float* b1  = (const float*)d_in[4];
    const float* W2  = (const float*)d_in[5];
    const float* b2  = (const float*)d_in[6];
    float*       out = (float*)d_out;

    const int* src = ei;
    const int* dst = ei + N_EDGES;

    // CSR build + norm
    k_zero   <<<(N_NODES + 255) / 256, 256>>>();
    k_hist   <<<(N_EDGES + 255) / 256, 256>>>(dst, ew);
    k_scan   <<<1, 256>>>();
    k_permute<<<(N_EDGES + 255) / 256, 256>>>(src, dst, ew);

    // ---- layer 1 ----
    k_gemm_scale<D_HID, 1><<<(N_NODES + 63) / 64, 256>>>(x, W1);
    k_gather64<<<(N_NODES * 32 + 255) / 256, 256>>>(b1);

    // ---- layer 2 ----
    k_gemm_scale<D_OUTF, 2><<<(N_NODES + 127) / 128, 256>>>(nullptr, W2);
    k_gather32<<<(N_NODES * 32 + 255) / 256, 256>>>(b2, out);
}